// round 14
// baseline (speedup 1.0000x reference)
#include <cuda_runtime.h>
#include <cuda_fp16.h>
#include <math.h>

#define NN 50000
#define NE 800000
#define FD 256
#define HEADS 4
#define CH 64
#define GG 782              // gemm blocks: (NN+63)/64
#define HG 3125             // hist blocks: (NE+255)/256

// ---- scratch (static device globals: no runtime allocation) ----
__device__ __half g_h[(size_t)NN * FD];    // GEMM output (fp16: agg sweet spot)
__device__ float  g_y[(size_t)NN * FD];    // layer-1 output (GEMM2 input)
__device__ float  g_asrc[NN * HEADS];
__device__ float  g_adst[NN * HEADS];
__device__ int    g_cnt[NN];               // static zero-init; scan re-zeros
__device__ int    g_off[NN + 1];
__device__ int    g_col[NE];               // CSR: src per position
__device__ int    g_pos[NE];               // per-edge intra-bucket position
__device__ int    g_done;                  // hist-block completion counter

__device__ __forceinline__ float lrelu(float x) { return fmaxf(x, 0.2f * x); }

__device__ __forceinline__ unsigned f2tf(float f) {
    unsigned u;
    asm("cvt.rna.tf32.f32 %0, %1;" : "=r"(u) : "f"(f));
    return u;
}

__device__ __forceinline__ void mma_tf32(float* c, const unsigned* a, const unsigned* b) {
    asm volatile(
        "mma.sync.aligned.m16n8k8.row.col.f32.tf32.tf32.f32 "
        "{%0,%1,%2,%3},{%4,%5,%6,%7},{%8,%9},{%0,%1,%2,%3};"
        : "+f"(c[0]), "+f"(c[1]), "+f"(c[2]), "+f"(c[3])
        : "r"(a[0]), "r"(a[1]), "r"(a[2]), "r"(a[3]), "r"(b[0]), "r"(b[1]));
}

// ---------------- fused GEMM + hist + (last-block) scan ----------------
// blocks [0,GG): R6 tf32 GEMM. blocks [GG,GG+HG): edge histogram; the LAST
// hist block to finish (g_done counter) runs the CSR exclusive scan
// device-side — the scan rides in gemm1's shadow, off the critical path.
__global__ void __launch_bounds__(256) k_gemm_att(
    const float* __restrict__ Ain,          // nullptr -> use g_y
    const float* __restrict__ W,
    const float* __restrict__ att_s,
    const float* __restrict__ att_d,
    const int* __restrict__ dstv)           // non-null: hist blocks appended
{
    if (blockIdx.x >= GG) {                 // -------- histogram branch -----
        const int e = (blockIdx.x - GG) * 256 + threadIdx.x;
        if (e < NE)
            g_pos[e] = atomicAdd(&g_cnt[dstv[e]], 1);
        __threadfence();                    // publish g_pos before signaling
        __syncthreads();
        __shared__ int s_last;
        if (threadIdx.x == 0)
            s_last = (atomicAdd(&g_done, 1) == HG - 1) ? 1 : 0;
        __syncthreads();
        if (!s_last) return;
        __threadfence();                    // acquire all blocks' g_cnt

        // ---- exclusive scan of g_cnt -> g_off (256 threads) ----
        const int PER = (NN + 255) / 256;   // 196
        __shared__ int wsum[8];
        const int t = threadIdx.x, lane = t & 31, wd = t >> 5;
        const int base = t * PER;
        int sum = 0;
        for (int i = 0; i < PER; i++) {
            int idx = base + i;
            if (idx < NN) sum += g_cnt[idx];
        }
        int v = sum;
#pragma unroll
        for (int o = 1; o < 32; o <<= 1) {
            int n = __shfl_up_sync(0xffffffffu, v, o);
            if (lane >= o) v += n;
        }
        if (lane == 31) wsum[wd] = v;
        __syncthreads();
        if (wd == 0) {
            int wv = (lane < 8) ? wsum[lane] : 0;
#pragma unroll
            for (int o = 1; o < 8; o <<= 1) {
                int n = __shfl_up_sync(0xffffffffu, wv, o);
                if (lane >= o) wv += n;
            }
            if (lane < 8) wsum[lane] = wv;
        }
        __syncthreads();
        int run = v - sum + (wd > 0 ? wsum[wd - 1] : 0);
        for (int i = 0; i < PER; i++) {
            int idx = base + i;
            if (idx < NN) {
                int c = g_cnt[idx];
                g_off[idx] = run;
                run += c;
                g_cnt[idx] = 0;             // reset for next graph replay
            }
        }
        if (t == 0) { g_off[NN] = wsum[7]; g_done = 0; }
        return;
    }
    // ------------------------------- GEMM branch ---------------------------
    const float* A = Ain ? Ain : g_y;
    __shared__ unsigned sAf[2][1024];       // fragment-major A (4KB/stage)
    __shared__ unsigned sB[2][16][264];     // [k][n] stride 264 (conflict-free)

    const int t    = threadIdx.x;
    const int lane = t & 31;
    const int wid  = t >> 5;
    const int gid  = lane >> 2, tig = lane & 3;
    const int wm   = wid & 1,   wn  = wid >> 1;   // rows wm*32, cols wn*64
    const int row0 = blockIdx.x * 64;

    float acc[2][8][4] = {};

    const int ar = t >> 2, acb = (t & 3) * 4;     // A: row ar, cols acb..acb+3
    const int br = t >> 4, bc = (t & 15) * 4;     // B: row br, 4x 64-strided float4
    const bool arow_ok = (row0 + ar) < NN;
    const float* aptr = A + (size_t)(row0 + ar) * FD + acb;
    const float* bptr = W + (size_t)br * FD + bc;

    int a_st[4];
    {
        const int wm_s = ar >> 5, tm_s = (ar >> 4) & 1;
        const int rh_s = (ar >> 3) & 1, gid_s = ar & 7;
#pragma unroll
        for (int j = 0; j < 4; j++) {
            const int k = acb + j;
            const int kkb = k >> 3, tg = k & 3, kh = (k >> 2) & 1;
            a_st[j] = (kkb * 128 + wm_s * 64 + tm_s * 32 + gid_s * 4 + tg) * 4
                      + rh_s + 2 * kh;
        }
    }
    const int a_rd0 = (wm * 64 + gid * 4 + tig) * 4;
    const int b_rd  = tig * 264 + wn * 64 + gid;

    float4 aval = make_float4(0.f, 0.f, 0.f, 0.f);
    float4 bval[4];
    if (arow_ok) aval = *(const float4*)aptr;
#pragma unroll
    for (int sub = 0; sub < 4; sub++)
        bval[sub] = *(const float4*)(bptr + sub * 64);

    int st = 0;
    for (int k0 = 0; k0 < FD; k0 += 16) {
        sAf[st][a_st[0]] = f2tf(aval.x);
        sAf[st][a_st[1]] = f2tf(aval.y);
        sAf[st][a_st[2]] = f2tf(aval.z);
        sAf[st][a_st[3]] = f2tf(aval.w);
#pragma unroll
        for (int sub = 0; sub < 4; sub++)
            *(uint4*)&sB[st][br][bc + sub * 64] =
                make_uint4(f2tf(bval[sub].x), f2tf(bval[sub].y),
                           f2tf(bval[sub].z), f2tf(bval[sub].w));
        // prefetch next chunk BEFORE the barrier: LDGs issue during the
        // barrier drain, landing under the full compute section.
        if (k0 + 16 < FD) {
            aval = make_float4(0.f, 0.f, 0.f, 0.f);
            if (arow_ok) aval = *(const float4*)(aptr + k0 + 16);
#pragma unroll
            for (int sub = 0; sub < 4; sub++)
                bval[sub] = *(const float4*)(bptr + (size_t)(k0 + 16) * FD + sub * 64);
        }
        __syncthreads();

        const unsigned* sa = sAf[st];
        const unsigned* sb = &sB[st][0][0] + b_rd;
#pragma unroll
        for (int kkb = 0; kkb < 2; kkb++) {
            uint4 af0 = *(const uint4*)(sa + kkb * 512 + a_rd0);        // tm=0
            uint4 af1 = *(const uint4*)(sa + kkb * 512 + a_rd0 + 128);  // tm=1
            const unsigned* b0 = sb + kkb * (8 * 264);
            unsigned bf[8][2];
#pragma unroll
            for (int tn = 0; tn < 8; tn++) {
                bf[tn][0] = b0[tn * 8];
                bf[tn][1] = b0[4 * 264 + tn * 8];
            }
#pragma unroll
            for (int tn = 0; tn < 8; tn++) {
                mma_tf32(acc[0][tn], (const unsigned*)&af0, bf[tn]);
                mma_tf32(acc[1][tn], (const unsigned*)&af1, bf[tn]);
            }
        }
        st ^= 1;
    }

    // ---- epilogue: store h (fp16), fused per-head attention dots ----
    const int head = wn;
#pragma unroll
    for (int tm = 0; tm < 2; tm++) {
#pragma unroll
        for (int rh = 0; rh < 2; rh++) {
            const int r = row0 + wm * 32 + tm * 16 + rh * 8 + gid;
            const bool rok = r < NN;
            float s_ = 0.f, d_ = 0.f;
#pragma unroll
            for (int tn = 0; tn < 8; tn++) {
                const int c = wn * 64 + tn * 8 + 2 * tig;
                const float v0 = acc[tm][tn][rh * 2], v1 = acc[tm][tn][rh * 2 + 1];
                s_ = fmaf(v0, att_s[c], fmaf(v1, att_s[c + 1], s_));
                d_ = fmaf(v0, att_d[c], fmaf(v1, att_d[c + 1], d_));
                if (rok)
                    *(__half2*)(g_h + (size_t)r * FD + c) = __floats2half2_rn(v0, v1);
            }
            s_ += __shfl_xor_sync(0xffffffffu, s_, 1);
            s_ += __shfl_xor_sync(0xffffffffu, s_, 2);
            d_ += __shfl_xor_sync(0xffffffffu, d_, 1);
            d_ += __shfl_xor_sync(0xffffffffu, d_, 2);
            if (tig == 0 && rok) {
                g_asrc[r * HEADS + head] = s_;
                g_adst[r * HEADS + head] = d_;
            }
        }
    }
}

// ---------------- atomic-free scatter, 2 edges/thread ----------------
__global__ void k_scatter(const int* __restrict__ src, const int* __restrict__ dst) {
    const int i = (blockIdx.x * blockDim.x + threadIdx.x) * 2;
    if (i + 1 < NE) {
        const int2 d = *(const int2*)(dst + i);
        const int2 p = *(const int2*)(g_pos + i);
        const int2 s = *(const int2*)(src + i);
        const int o0 = g_off[d.x], o1 = g_off[d.y];
        g_col[o0 + p.x] = s.x;
        g_col[o1 + p.y] = s.y;
    } else if (i < NE) {
        g_col[g_off[dst[i]] + g_pos[i]] = src[i];
    }
}

// ---------------- per-dst-node aggregation (R11 verbatim) ----------------
// One warp per node; single pass, max-free softmax; fp16 h rows
// (1 LDG.128/lane/edge) + x4 batched unroll.
__global__ void __launch_bounds__(256) k_aggregate(
    const float* __restrict__ bias,
    float* __restrict__ outp)               // nullptr -> g_y
{
    const int w = (blockIdx.x * blockDim.x + threadIdx.x) >> 5;
    const int lane = threadIdx.x & 31;
    if (w >= NN) return;
    const int hd = lane >> 3;
    const float ad = g_adst[w * HEADS + hd];
    const int beg = g_off[w], end = g_off[w + 1];

    float wt = __expf(lrelu(g_asrc[w * HEADS + hd] + ad));   // self loop
    float denom = wt;
    float a0, a1, a2, a3, a4, a5, a6, a7;
    {
        const uint4 raw = *(const uint4*)(g_h + (size_t)w * FD + lane * 8);
        const __half2* hp = (const __half2*)&raw;
        const float2 f0 = __half22float2(hp[0]), f1 = __half22float2(hp[1]);
        const float2 f2 = __half22float2(hp[2]), f3 = __half22float2(hp[3]);
        a0 = wt * f0.x; a1 = wt * f0.y; a2 = wt * f1.x; a3 = wt * f1.y;
        a4 = wt * f2.x; a5 = wt * f2.y; a6 = wt * f3.x; a7 = wt * f3.y;
    }

    int k = beg;
    for (; k + 4 <= end; k += 4) {
        const int s0 = g_col[k], s1 = g_col[k + 1];
        const int s2 = g_col[k + 2], s3 = g_col[k + 3];
        const float e0 = g_asrc[s0 * HEADS + hd] + ad;
        const float e1 = g_asrc[s1 * HEADS + hd] + ad;
        const float e2 = g_asrc[s2 * HEADS + hd] + ad;
        const float e3 = g_asrc[s3 * HEADS + hd] + ad;
        const uint4 r0 = *(const uint4*)(g_h + (size_t)s0 * FD + lane * 8);
        const uint4 r1 = *(const uint4*)(g_h + (size_t)s1 * FD + lane * 8);
        const uint4 r2 = *(const uint4*)(g_h + (size_t)s2 * FD + lane * 8);
        const uint4 r3 = *(const uint4*)(g_h + (size_t)s3 * FD + lane * 8);
        const float w0 = __expf(lrelu(e0)), w1 = __expf(lrelu(e1));
        const float w2 = __expf(lrelu(e2)), w3 = __expf(lrelu(e3));
        denom += (w0 + w1) + (w2 + w3);
        const __half2* p0 = (const __half2*)&r0;
        const __half2* p1 = (const __half2*)&r1;
        const __half2* p2 = (const __half2*)&r2;
        const __half2* p3 = (const __half2*)&r3;
#define ACC8(pp, ww) { \
        const float2 x0 = __half22float2((pp)[0]), x1 = __half22float2((pp)[1]); \
        const float2 x2 = __half22float2((pp)[2]), x3 = __half22float2((pp)[3]); \
        a0 = fmaf((ww), x0.x, a0); a1 = fmaf((ww), x0.y, a1); \
        a2 = fmaf((ww), x1.x, a2); a3 = fmaf((ww), x1.y, a3); \
        a4 = fmaf((ww), x2.x, a4); a5 = fmaf((ww), x2.y, a5); \
        a6 = fmaf((ww), x3.x, a6); a7 = fmaf((ww), x3.y, a7); }
        ACC8(p0, w0) ACC8(p1, w1) ACC8(p2, w2) ACC8(p3, w3)
    }
    for (; k < end; k++) {
        const int s = g_col[k];
        const float wt1 = __expf(lrelu(g_asrc[s * HEADS + hd] + ad));
        denom += wt1;
        const uint4 raw = *(const uint4*)(g_h + (size_t)s * FD + lane * 8);
        const __half2* hp = (const __half2*)&raw;
        ACC8(hp, wt1)
    }
#undef ACC8

    const float inv = 1.0f / (denom + 1e-16f);
    const float* bp = bias + lane * 8;
    float r0 = a0 * inv + bp[0], r1 = a1 * inv + bp[1];
    float r2 = a2 * inv + bp[2], r3 = a3 * inv + bp[3];
    float r4 = a4 * inv + bp[4], r5 = a5 * inv + bp[5];
    float r6 = a6 * inv + bp[6], r7 = a7 * inv + bp[7];
    r0 = r0 > 0.f ? r0 : expm1f(r0);  r1 = r1 > 0.f ? r1 : expm1f(r1);
    r2 = r2 > 0.f ? r2 : expm1f(r2);  r3 = r3 > 0.f ? r3 : expm1f(r3);
    r4 = r4 > 0.f ? r4 : expm1f(r4);  r5 = r5 > 0.f ? r5 : expm1f(r5);
    r6 = r6 > 0.f ? r6 : expm1f(r6);  r7 = r7 > 0.f ? r7 : expm1f(r7);

    float* op = (outp ? outp : g_y) + (size_t)w * FD + lane * 8;
    *(float4*)op       = make_float4(r0, r1, r2, r3);
    *((float4*)op + 1) = make_float4(r4, r5, r6, r7);
}

// ---------------- launch ----------------
extern "C" void kernel_launch(void* const* d_in, const int* in_sizes, int n_in,
                              void* d_out, int out_size)
{
    const float* x   = (const float*)d_in[0];
    const int*   ei  = (const int*)d_in[1];
    const float* W1  = (const float*)d_in[2];
    const float* as1 = (const float*)d_in[3];
    const float* ad1 = (const float*)d_in[4];
    const float* b1  = (const float*)d_in[5];
    const float* W2  = (const float*)d_in[6];
    const float* as2 = (const float*)d_in[7];
    const float* ad2 = (const float*)d_in[8];
    const float* b2  = (const float*)d_in[9];

    const int* src = ei;            // edge_index row 0
    const int* dst = ei + NE;       // edge_index row 1

    const int agrid = (NN * 32 + 255) / 256;
    const int sgrid = (NE / 2 + 255) / 256;

    // 5 launches: gemm1||hist||scan fused -> scatter -> agg1 -> gemm2 -> agg2
    k_gemm_att<<<GG + HG, 256>>>(x, W1, as1, ad1, dst);
    k_scatter<<<sgrid, 256>>>(src, dst);
    k_aggregate<<<agrid, 256>>>(b1, nullptr);
    k_gemm_att<<<GG, 256>>>(nullptr, W2, as2, ad2, nullptr);   // <- profiled slot
    k_aggregate<<<agrid, 256>>>(b2, (float*)d_out);
}

// round 17
// speedup vs baseline: 1.1741x; 1.1741x over previous
#include <cuda_runtime.h>
#include <cuda_fp16.h>
#include <math.h>

#define NN 50000
#define NE 800000
#define FD 256
#define HEADS 4
#define CH 64
#define GG 782              // gemm blocks: (NN+63)/64
#define HG 3125             // hist blocks: (NE+255)/256

// ---- scratch (static device globals: no runtime allocation) ----
__device__ __half g_h[(size_t)NN * FD];    // GEMM output (fp16: agg sweet spot)
__device__ float  g_y[(size_t)NN * FD];    // layer-1 output (GEMM2 input)
__device__ float  g_asrc[NN * HEADS];
__device__ float  g_adst[NN * HEADS];
__device__ int    g_cnt[NN];               // static zero-init; scan re-zeros
__device__ int    g_off[NN + 1];
__device__ int    g_col[NE];               // CSR: src per position
__device__ int    g_pos[NE];               // per-edge intra-bucket position

__device__ __forceinline__ float lrelu(float x) { return fmaxf(x, 0.2f * x); }

__device__ __forceinline__ unsigned f2tf(float f) {
    unsigned u;
    asm("cvt.rna.tf32.f32 %0, %1;" : "=r"(u) : "f"(f));
    return u;
}

__device__ __forceinline__ void mma_tf32(float* c, const unsigned* a, const unsigned* b) {
    asm volatile(
        "mma.sync.aligned.m16n8k8.row.col.f32.tf32.tf32.f32 "
        "{%0,%1,%2,%3},{%4,%5,%6,%7},{%8,%9},{%0,%1,%2,%3};"
        : "+f"(c[0]), "+f"(c[1]), "+f"(c[2]), "+f"(c[3])
        : "r"(a[0]), "r"(a[1]), "r"(a[2]), "r"(a[3]), "r"(b[0]), "r"(b[1]));
}

// ---------------- fused GEMM + hist ----------------
// blocks [0,GG): R6 tf32 GEMM (block 64x256, 8 warps = 2wm x 4wn, warp 32x64,
//   fragment-major A, double-buffered smem, prefetch-before-barrier, fused
//   attention-logit epilogue).
// blocks [GG, GG+HG): edge histogram (independent work, overlaps the GEMM;
//   NO fences/atinc machinery — plain R11 version).
__global__ void __launch_bounds__(256) k_gemm_att(
    const float* __restrict__ Ain,          // nullptr -> use g_y
    const float* __restrict__ W,
    const float* __restrict__ att_s,
    const float* __restrict__ att_d,
    const int* __restrict__ dstv)           // non-null: hist blocks appended
{
    if (blockIdx.x >= GG) {                 // -------- histogram branch -----
        const int e = (blockIdx.x - GG) * 256 + threadIdx.x;
        if (e < NE)
            g_pos[e] = atomicAdd(&g_cnt[dstv[e]], 1);
        return;
    }
    // ------------------------------- GEMM branch ---------------------------
    const float* A = Ain ? Ain : g_y;
    __shared__ unsigned sAf[2][1024];       // fragment-major A (4KB/stage)
    __shared__ unsigned sB[2][16][264];     // [k][n] stride 264 (conflict-free)

    const int t    = threadIdx.x;
    const int lane = t & 31;
    const int wid  = t >> 5;
    const int gid  = lane >> 2, tig = lane & 3;
    const int wm   = wid & 1,   wn  = wid >> 1;   // rows wm*32, cols wn*64
    const int row0 = blockIdx.x * 64;

    float acc[2][8][4] = {};

    const int ar = t >> 2, acb = (t & 3) * 4;     // A: row ar, cols acb..acb+3
    const int br = t >> 4, bc = (t & 15) * 4;     // B: row br, 4x 64-strided float4
    const bool arow_ok = (row0 + ar) < NN;
    const float* aptr = A + (size_t)(row0 + ar) * FD + acb;
    const float* bptr = W + (size_t)br * FD + bc;

    int a_st[4];
    {
        const int wm_s = ar >> 5, tm_s = (ar >> 4) & 1;
        const int rh_s = (ar >> 3) & 1, gid_s = ar & 7;
#pragma unroll
        for (int j = 0; j < 4; j++) {
            const int k = acb + j;
            const int kkb = k >> 3, tg = k & 3, kh = (k >> 2) & 1;
            a_st[j] = (kkb * 128 + wm_s * 64 + tm_s * 32 + gid_s * 4 + tg) * 4
                      + rh_s + 2 * kh;
        }
    }
    const int a_rd0 = (wm * 64 + gid * 4 + tig) * 4;
    const int b_rd  = tig * 264 + wn * 64 + gid;

    float4 aval = make_float4(0.f, 0.f, 0.f, 0.f);
    float4 bval[4];
    if (arow_ok) aval = *(const float4*)aptr;
#pragma unroll
    for (int sub = 0; sub < 4; sub++)
        bval[sub] = *(const float4*)(bptr + sub * 64);

    int st = 0;
    for (int k0 = 0; k0 < FD; k0 += 16) {
        sAf[st][a_st[0]] = f2tf(aval.x);
        sAf[st][a_st[1]] = f2tf(aval.y);
        sAf[st][a_st[2]] = f2tf(aval.z);
        sAf[st][a_st[3]] = f2tf(aval.w);
#pragma unroll
        for (int sub = 0; sub < 4; sub++)
            *(uint4*)&sB[st][br][bc + sub * 64] =
                make_uint4(f2tf(bval[sub].x), f2tf(bval[sub].y),
                           f2tf(bval[sub].z), f2tf(bval[sub].w));
        // prefetch next chunk BEFORE the barrier (validated: 69.1 -> 67.5us):
        // LDGs issue during the barrier drain, landing under the compute section.
        if (k0 + 16 < FD) {
            aval = make_float4(0.f, 0.f, 0.f, 0.f);
            if (arow_ok) aval = *(const float4*)(aptr + k0 + 16);
#pragma unroll
            for (int sub = 0; sub < 4; sub++)
                bval[sub] = *(const float4*)(bptr + (size_t)(k0 + 16) * FD + sub * 64);
        }
        __syncthreads();

        const unsigned* sa = sAf[st];
        const unsigned* sb = &sB[st][0][0] + b_rd;
#pragma unroll
        for (int kkb = 0; kkb < 2; kkb++) {
            uint4 af0 = *(const uint4*)(sa + kkb * 512 + a_rd0);        // tm=0
            uint4 af1 = *(const uint4*)(sa + kkb * 512 + a_rd0 + 128);  // tm=1
            const unsigned* b0 = sb + kkb * (8 * 264);
            unsigned bf[8][2];
#pragma unroll
            for (int tn = 0; tn < 8; tn++) {
                bf[tn][0] = b0[tn * 8];
                bf[tn][1] = b0[4 * 264 + tn * 8];
            }
#pragma unroll
            for (int tn = 0; tn < 8; tn++) {
                mma_tf32(acc[0][tn], (const unsigned*)&af0, bf[tn]);
                mma_tf32(acc[1][tn], (const unsigned*)&af1, bf[tn]);
            }
        }
        st ^= 1;
    }

    // ---- epilogue: store h (fp16), fused per-head attention dots ----
    const int head = wn;
#pragma unroll
    for (int tm = 0; tm < 2; tm++) {
#pragma unroll
        for (int rh = 0; rh < 2; rh++) {
            const int r = row0 + wm * 32 + tm * 16 + rh * 8 + gid;
            const bool rok = r < NN;
            float s_ = 0.f, d_ = 0.f;
#pragma unroll
            for (int tn = 0; tn < 8; tn++) {
                const int c = wn * 64 + tn * 8 + 2 * tig;
                const float v0 = acc[tm][tn][rh * 2], v1 = acc[tm][tn][rh * 2 + 1];
                s_ = fmaf(v0, att_s[c], fmaf(v1, att_s[c + 1], s_));
                d_ = fmaf(v0, att_d[c], fmaf(v1, att_d[c + 1], d_));
                if (rok)
                    *(__half2*)(g_h + (size_t)r * FD + c) = __floats2half2_rn(v0, v1);
            }
            s_ += __shfl_xor_sync(0xffffffffu, s_, 1);
            s_ += __shfl_xor_sync(0xffffffffu, s_, 2);
            d_ += __shfl_xor_sync(0xffffffffu, d_, 1);
            d_ += __shfl_xor_sync(0xffffffffu, d_, 2);
            if (tig == 0 && rok) {
                g_asrc[r * HEADS + head] = s_;
                g_adst[r * HEADS + head] = d_;
            }
        }
    }
}

// ---------------- scan: exclusive prefix of g_cnt -> g_off, re-zero g_cnt ----
__global__ void k_scan() {
    const int T = 1024, PER = (NN + T - 1) / T;   // 49
    __shared__ int wsum[32];
    const int t = threadIdx.x, lane = t & 31, wid = t >> 5;
    const int base = t * PER;

    int sum = 0;
    for (int i = 0; i < PER; i++) {
        int idx = base + i;
        if (idx < NN) sum += g_cnt[idx];
    }
    int v = sum;
#pragma unroll
    for (int o = 1; o < 32; o <<= 1) {
        int n = __shfl_up_sync(0xffffffffu, v, o);
        if (lane >= o) v += n;
    }
    if (lane == 31) wsum[wid] = v;
    __syncthreads();
    if (wid == 0) {
        int wv = wsum[lane];
#pragma unroll
        for (int o = 1; o < 32; o <<= 1) {
            int n = __shfl_up_sync(0xffffffffu, wv, o);
            if (lane >= o) wv += n;
        }
        wsum[lane] = wv;
    }
    __syncthreads();
    int run = v - sum + (wid > 0 ? wsum[wid - 1] : 0);
    for (int i = 0; i < PER; i++) {
        int idx = base + i;
        if (idx < NN) {
            int c = g_cnt[idx];
            g_off[idx] = run;
            run += c;
            g_cnt[idx] = 0;                  // reset for next call's hist
        }
    }
    if (t == 0) g_off[NN] = wsum[31];
}

// ---------------- atomic-free scatter, 2 edges/thread ----------------
__global__ void k_scatter(const int* __restrict__ src, const int* __restrict__ dst) {
    const int i = (blockIdx.x * blockDim.x + threadIdx.x) * 2;
    if (i + 1 < NE) {
        const int2 d = *(const int2*)(dst + i);
        const int2 p = *(const int2*)(g_pos + i);
        const int2 s = *(const int2*)(src + i);
        const int o0 = g_off[d.x], o1 = g_off[d.y];
        g_col[o0 + p.x] = s.x;
        g_col[o1 + p.y] = s.y;
    } else if (i < NE) {
        g_col[g_off[dst[i]] + g_pos[i]] = src[i];
    }
}

// ---------------- per-dst-node aggregation (R11 verbatim) ----------------
// One warp per node; single pass, max-free softmax; fp16 h rows
// (1 LDG.128/lane/edge) + x4 batched unroll.
__global__ void __launch_bounds__(256) k_aggregate(
    const float* __restrict__ bias,
    float* __restrict__ outp)               // nullptr -> g_y
{
    const int w = (blockIdx.x * blockDim.x + threadIdx.x) >> 5;
    const int lane = threadIdx.x & 31;
    if (w >= NN) return;
    const int hd = lane >> 3;
    const float ad = g_adst[w * HEADS + hd];
    const int beg = g_off[w], end = g_off[w + 1];

    float wt = __expf(lrelu(g_asrc[w * HEADS + hd] + ad));   // self loop
    float denom = wt;
    float a0, a1, a2, a3, a4, a5, a6, a7;
    {
        const uint4 raw = *(const uint4*)(g_h + (size_t)w * FD + lane * 8);
        const __half2* hp = (const __half2*)&raw;
        const float2 f0 = __half22float2(hp[0]), f1 = __half22float2(hp[1]);
        const float2 f2 = __half22float2(hp[2]), f3 = __half22float2(hp[3]);
        a0 = wt * f0.x; a1 = wt * f0.y; a2 = wt * f1.x; a3 = wt * f1.y;
        a4 = wt * f2.x; a5 = wt * f2.y; a6 = wt * f3.x; a7 = wt * f3.y;
    }

    int k = beg;
    for (; k + 4 <= end; k += 4) {
        const int s0 = g_col[k], s1 = g_col[k + 1];
        const int s2 = g_col[k + 2], s3 = g_col[k + 3];
        const float e0 = g_asrc[s0 * HEADS + hd] + ad;
        const float e1 = g_asrc[s1 * HEADS + hd] + ad;
        const float e2 = g_asrc[s2 * HEADS + hd] + ad;
        const float e3 = g_asrc[s3 * HEADS + hd] + ad;
        const uint4 r0 = *(const uint4*)(g_h + (size_t)s0 * FD + lane * 8);
        const uint4 r1 = *(const uint4*)(g_h + (size_t)s1 * FD + lane * 8);
        const uint4 r2 = *(const uint4*)(g_h + (size_t)s2 * FD + lane * 8);
        const uint4 r3 = *(const uint4*)(g_h + (size_t)s3 * FD + lane * 8);
        const float w0 = __expf(lrelu(e0)), w1 = __expf(lrelu(e1));
        const float w2 = __expf(lrelu(e2)), w3 = __expf(lrelu(e3));
        denom += (w0 + w1) + (w2 + w3);
        const __half2* p0 = (const __half2*)&r0;
        const __half2* p1 = (const __half2*)&r1;
        const __half2* p2 = (const __half2*)&r2;
        const __half2* p3 = (const __half2*)&r3;
#define ACC8(pp, ww) { \
        const float2 x0 = __half22float2((pp)[0]), x1 = __half22float2((pp)[1]); \
        const float2 x2 = __half22float2((pp)[2]), x3 = __half22float2((pp)[3]); \
        a0 = fmaf((ww), x0.x, a0); a1 = fmaf((ww), x0.y, a1); \
        a2 = fmaf((ww), x1.x, a2); a3 = fmaf((ww), x1.y, a3); \
        a4 = fmaf((ww), x2.x, a4); a5 = fmaf((ww), x2.y, a5); \
        a6 = fmaf((ww), x3.x, a6); a7 = fmaf((ww), x3.y, a7); }
        ACC8(p0, w0) ACC8(p1, w1) ACC8(p2, w2) ACC8(p3, w3)
    }
    for (; k < end; k++) {
        const int s = g_col[k];
        const float wt1 = __expf(lrelu(g_asrc[s * HEADS + hd] + ad));
        denom += wt1;
        const uint4 raw = *(const uint4*)(g_h + (size_t)s * FD + lane * 8);
        const __half2* hp = (const __half2*)&raw;
        ACC8(hp, wt1)
    }
#undef ACC8

    const float inv = 1.0f / (denom + 1e-16f);
    const float* bp = bias + lane * 8;
    float r0 = a0 * inv + bp[0], r1 = a1 * inv + bp[1];
    float r2 = a2 * inv + bp[2], r3 = a3 * inv + bp[3];
    float r4 = a4 * inv + bp[4], r5 = a5 * inv + bp[5];
    float r6 = a6 * inv + bp[6], r7 = a7 * inv + bp[7];
    r0 = r0 > 0.f ? r0 : expm1f(r0);  r1 = r1 > 0.f ? r1 : expm1f(r1);
    r2 = r2 > 0.f ? r2 : expm1f(r2);  r3 = r3 > 0.f ? r3 : expm1f(r3);
    r4 = r4 > 0.f ? r4 : expm1f(r4);  r5 = r5 > 0.f ? r5 : expm1f(r5);
    r6 = r6 > 0.f ? r6 : expm1f(r6);  r7 = r7 > 0.f ? r7 : expm1f(r7);

    float* op = (outp ? outp : g_y) + (size_t)w * FD + lane * 8;
    *(float4*)op       = make_float4(r0, r1, r2, r3);
    *((float4*)op + 1) = make_float4(r4, r5, r6, r7);
}

// ---------------- launch ----------------
extern "C" void kernel_launch(void* const* d_in, const int* in_sizes, int n_in,
                              void* d_out, int out_size)
{
    const float* x   = (const float*)d_in[0];
    const int*   ei  = (const int*)d_in[1];
    const float* W1  = (const float*)d_in[2];
    const float* as1 = (const float*)d_in[3];
    const float* ad1 = (const float*)d_in[4];
    const float* b1  = (const float*)d_in[5];
    const float* W2  = (const float*)d_in[6];
    const float* as2 = (const float*)d_in[7];
    const float* ad2 = (const float*)d_in[8];
    const float* b2  = (const float*)d_in[9];

    const int* src = ei;            // edge_index row 0
    const int* dst = ei + NE;       // edge_index row 1

    const int agrid = (NN * 32 + 255) / 256;
    const int sgrid = (NE / 2 + 255) / 256;

    // 6 launches (R11 structure)
    k_gemm_att<<<GG + HG, 256>>>(x, W1, as1, ad1, dst);   // gemm1 || hist
    k_scan<<<1, 1024>>>();                                // prefix + re-zero
    k_scatter<<<sgrid, 256>>>(src, dst);                  // atomic-free, x2
    k_aggregate<<<agrid, 256>>>(b1, nullptr);
    k_gemm_att<<<GG, 256>>>(nullptr, W2, as2, ad2, nullptr);
    k_aggregate<<<agrid, 256>>>(b2, (float*)d_out);
}